// round 5
// baseline (speedup 1.0000x reference)
#include <cuda_runtime.h>
#include <cstdint>

// Problem constants (GCN_59846074302981): N=50000, E=800000, F=H=128, C=8
#define MAX_N 50000
#define MAX_E 800000

// ---------------------------------------------------------------------------
// Scratch (allocation-free device globals)
// ---------------------------------------------------------------------------
__device__ __align__(16) float g_bufA[MAX_N * 128];  // GEMM out / agg in
__device__ __align__(16) float g_bufB[MAX_N * 128];  // agg out / next GEMM in
__device__ __align__(16) float g_dinv[MAX_N];
__device__ __align__(16) float g_w[MAX_E];           // edge norm per CSR slot
__device__ int   g_count[MAX_N];                     // histogram, then fill cursor
__device__ int   g_off[MAX_N + 1];                   // CSR offsets (by dest col)
__device__ int   g_srcIdx[MAX_E];                    // source node per CSR slot
__device__ int   g_stride;                           // 1 = int32 edge data, 2 = int64

__device__ __forceinline__ int edge_at(const int* __restrict__ buf, long j, int stride) {
    return buf[j * stride];
}

// ---------------------------------------------------------------------------
// init: zero counts; block 0 thread 0 also probes edge dtype.
// int64 data with indices < 2^31 has every odd int32 word == 0.
// ---------------------------------------------------------------------------
__global__ void k_init(const int* __restrict__ ebuf, int n) {
    int i = blockIdx.x * blockDim.x + threadIdx.x;
    if (i < n) g_count[i] = 0;
    if (i == 0) {
        int is64 = 1;
        #pragma unroll 1
        for (int t = 0; t < 256; t++)
            if (ebuf[2 * t + 1] != 0) { is64 = 0; break; }
        g_stride = is64 ? 2 : 1;
    }
}

__global__ void k_hist(const int* __restrict__ ebuf, int e, int n) {
    int i = blockIdx.x * blockDim.x + threadIdx.x;
    if (i >= e) return;
    int st = g_stride;
    int c = edge_at(ebuf, (long)e + i, st);
    if ((unsigned)c < (unsigned)n) atomicAdd(&g_count[c], 1);
}

// Single-block scan. Also computes dinv and re-zeroes counts (fill cursors).
__global__ __launch_bounds__(1024) void k_scan(int n) {
    const int T = 1024;
    int tid  = threadIdx.x;
    int L    = (n + T - 1) / T;
    int beg  = tid * L;
    int end  = beg + L; if (end > n) end = n;

    int s = 0;
    for (int i = beg; i < end; i++) s += g_count[i];

    __shared__ int wsum[32];
    int lane = tid & 31, wid = tid >> 5;
    int v = s;
    #pragma unroll
    for (int o = 1; o < 32; o <<= 1) {
        int t = __shfl_up_sync(0xffffffffu, v, o);
        if (lane >= o) v += t;
    }
    if (lane == 31) wsum[wid] = v;
    __syncthreads();
    if (wid == 0) {
        int w = wsum[lane];
        #pragma unroll
        for (int o = 1; o < 32; o <<= 1) {
            int t = __shfl_up_sync(0xffffffffu, w, o);
            if (lane >= o) w += t;
        }
        wsum[lane] = w;
    }
    __syncthreads();

    int run = v - s + (wid ? wsum[wid - 1] : 0);
    for (int i = beg; i < end; i++) {
        int c = g_count[i];
        g_off[i]   = run;
        g_dinv[i]  = rsqrtf((float)c + 1.0f);   // +1 self-loop
        g_count[i] = 0;                          // cursor for fill
        run += c;
    }
    if (tid == T - 1) g_off[n] = run;
}

__global__ void k_fill(const int* __restrict__ ebuf, int e, int n) {
    int i = blockIdx.x * blockDim.x + threadIdx.x;
    if (i >= e) return;
    int st = g_stride;
    int r = edge_at(ebuf, i, st);
    int c = edge_at(ebuf, (long)e + i, st);
    if ((unsigned)r >= (unsigned)n || (unsigned)c >= (unsigned)n) return;
    int slot = g_off[c] + atomicAdd(&g_count[c], 1);
    g_srcIdx[slot] = r;
    g_w[slot] = g_dinv[r] * g_dinv[c];
}

// ---------------------------------------------------------------------------
// GEMM: g_bufA[n,128] = SRC[n,128] @ W[128,128]
// 128x128 block tile, BK=16, 256 thr, 8x8 per thread, register prefetch.
// ---------------------------------------------------------------------------
__global__ __launch_bounds__(256) void k_gemm128(const float* __restrict__ Xext,
                                                 const float* __restrict__ W,
                                                 int use_ext, int nrows) {
    const float* __restrict__ X = use_ext ? Xext : g_bufB;
    const float4* __restrict__ X4 = reinterpret_cast<const float4*>(X);
    const float4* __restrict__ W4 = reinterpret_cast<const float4*>(W);

    __shared__ __align__(16) float xs[16][132];   // [k][m] transposed
    __shared__ __align__(16) float ws[16][128];   // [k][n]

    const int row0 = blockIdx.x * 128;
    const int tid  = threadIdx.x;
    const int tm   = (tid >> 4) << 3;   // 0..120 step 8
    const int tn   = (tid & 15) << 3;   // 0..120 step 8

    // Load mapping
    const int xr = tid >> 2;            // 0..63 (plus +64 for second)
    const int xc = tid & 3;             // float4 slot within 16-wide K chunk
    const int wk = tid >> 5;            // 0..7 (plus +8)
    const int wc = tid & 31;            // float4 slot in 128-wide N

    const float4 z4 = make_float4(0.f, 0.f, 0.f, 0.f);
    float4 pa0, pa1, pw0, pw1;

    float acc[8][8];
    #pragma unroll
    for (int i = 0; i < 8; i++)
        #pragma unroll
        for (int j = 0; j < 8; j++) acc[i][j] = 0.0f;

    // prefetch chunk 0
    {
        int r0 = row0 + xr, r1 = row0 + xr + 64;
        pa0 = (r0 < nrows) ? X4[(long)r0 * 32 + xc] : z4;
        pa1 = (r1 < nrows) ? X4[(long)r1 * 32 + xc] : z4;
        pw0 = W4[(long)wk * 32 + wc];
        pw1 = W4[(long)(wk + 8) * 32 + wc];
    }

    #pragma unroll 1
    for (int kk = 0; kk < 8; kk++) {
        // store prefetched chunk
        {
            int c0 = xc << 2;
            xs[c0 + 0][xr] = pa0.x; xs[c0 + 1][xr] = pa0.y;
            xs[c0 + 2][xr] = pa0.z; xs[c0 + 3][xr] = pa0.w;
            xs[c0 + 0][xr + 64] = pa1.x; xs[c0 + 1][xr + 64] = pa1.y;
            xs[c0 + 2][xr + 64] = pa1.z; xs[c0 + 3][xr + 64] = pa1.w;
            *reinterpret_cast<float4*>(&ws[wk][wc << 2])     = pw0;
            *reinterpret_cast<float4*>(&ws[wk + 8][wc << 2]) = pw1;
        }
        __syncthreads();

        // prefetch next chunk
        if (kk < 7) {
            int k4 = (kk + 1) << 2;
            int r0 = row0 + xr, r1 = row0 + xr + 64;
            pa0 = (r0 < nrows) ? X4[(long)r0 * 32 + k4 + xc] : z4;
            pa1 = (r1 < nrows) ? X4[(long)r1 * 32 + k4 + xc] : z4;
            pw0 = W4[(long)((kk + 1) * 16 + wk) * 32 + wc];
            pw1 = W4[(long)((kk + 1) * 16 + wk + 8) * 32 + wc];
        }

        // compute 16 k-steps
        #pragma unroll
        for (int k = 0; k < 16; k++) {
            float4 a0 = *reinterpret_cast<const float4*>(&xs[k][tm]);
            float4 a1 = *reinterpret_cast<const float4*>(&xs[k][tm + 4]);
            float4 b0 = *reinterpret_cast<const float4*>(&ws[k][tn]);
            float4 b1 = *reinterpret_cast<const float4*>(&ws[k][tn + 4]);
            float a[8] = {a0.x, a0.y, a0.z, a0.w, a1.x, a1.y, a1.z, a1.w};
            float b[8] = {b0.x, b0.y, b0.z, b0.w, b1.x, b1.y, b1.z, b1.w};
            #pragma unroll
            for (int i = 0; i < 8; i++)
                #pragma unroll
                for (int j = 0; j < 8; j++)
                    acc[i][j] += a[i] * b[j];
        }
        __syncthreads();
    }

    #pragma unroll
    for (int i = 0; i < 8; i++) {
        int r = row0 + tm + i;
        if (r < nrows) {
            reinterpret_cast<float4*>(g_bufA)[(long)r * 32 + (tn >> 2) + 0] =
                make_float4(acc[i][0], acc[i][1], acc[i][2], acc[i][3]);
            reinterpret_cast<float4*>(g_bufA)[(long)r * 32 + (tn >> 2) + 1] =
                make_float4(acc[i][4], acc[i][5], acc[i][6], acc[i][7]);
        }
    }
}

// ---------------------------------------------------------------------------
// Aggregation (atomic-free): one warp per node, lane owns one float4 of H=128.
// result = bias + dinv^2 * h[node] + sum_{e->node} w_e * h[src_e]
// If Wfc != nullptr: fused classifier, writes out[node,8]; else writes g_bufB.
// ---------------------------------------------------------------------------
__global__ __launch_bounds__(256) void k_aggregate(const float* __restrict__ bias,
                                                   const float* __restrict__ Wfc,
                                                   const float* __restrict__ bfc,
                                                   float* __restrict__ out, int n) {
    __shared__ __align__(16) float wfcT[8][128];   // [c][k]
    __shared__ float bs[8];

    const int tid  = threadIdx.x;
    const int lane = tid & 31;
    const int fc   = (Wfc != nullptr);

    if (fc) {
        #pragma unroll
        for (int i = 0; i < 4; i++) {
            int idx = tid + i * 256;           // 0..1023 over Wfc[128][8]
            wfcT[idx & 7][idx >> 3] = Wfc[idx];
        }
        if (tid < 8) bs[tid] = bfc[tid];
        __syncthreads();
    }

    int warp = blockIdx.x * (blockDim.x >> 5) + (tid >> 5);
    if (warp >= n) return;

    const float4* __restrict__ h4 = reinterpret_cast<const float4*>(g_bufA);

    float d = g_dinv[warp];
    float s = d * d;
    float4 b  = reinterpret_cast<const float4*>(bias)[lane];
    float4 hv = h4[(long)warp * 32 + lane];
    float ax = b.x + s * hv.x, ay = b.y + s * hv.y;
    float az = b.z + s * hv.z, aw = b.w + s * hv.w;

    int j   = g_off[warp];
    int end = g_off[warp + 1];

    for (; j + 3 < end; j += 4) {
        int   r0 = g_srcIdx[j],     r1 = g_srcIdx[j + 1];
        int   r2 = g_srcIdx[j + 2], r3 = g_srcIdx[j + 3];
        float w0 = g_w[j],     w1 = g_w[j + 1];
        float w2 = g_w[j + 2], w3 = g_w[j + 3];
        float4 v0 = h4[(long)r0 * 32 + lane];
        float4 v1 = h4[(long)r1 * 32 + lane];
        float4 v2 = h4[(long)r2 * 32 + lane];
        float4 v3 = h4[(long)r3 * 32 + lane];
        ax += w0 * v0.x; ay += w0 * v0.y; az += w0 * v0.z; aw += w0 * v0.w;
        ax += w1 * v1.x; ay += w1 * v1.y; az += w1 * v1.z; aw += w1 * v1.w;
        ax += w2 * v2.x; ay += w2 * v2.y; az += w2 * v2.z; aw += w2 * v2.w;
        ax += w3 * v3.x; ay += w3 * v3.y; az += w3 * v3.z; aw += w3 * v3.w;
    }
    for (; j < end; j++) {
        int   r0 = g_srcIdx[j];
        float w0 = g_w[j];
        float4 v0 = h4[(long)r0 * 32 + lane];
        ax += w0 * v0.x; ay += w0 * v0.y; az += w0 * v0.z; aw += w0 * v0.w;
    }

    if (!fc) {
        reinterpret_cast<float4*>(g_bufB)[(long)warp * 32 + lane] =
            make_float4(ax, ay, az, aw);
    } else {
        // fused classifier: y[c] = sum_k h_k WfcT[c][k] + bfc[c]
        float y[8];
        #pragma unroll
        for (int c = 0; c < 8; c++) {
            float4 w = *reinterpret_cast<const float4*>(&wfcT[c][lane << 2]);
            y[c] = ax * w.x + ay * w.y + az * w.z + aw * w.w;
        }
        #pragma unroll
        for (int o = 16; o > 0; o >>= 1)
            #pragma unroll
            for (int c = 0; c < 8; c++)
                y[c] += __shfl_xor_sync(0xffffffffu, y[c], o);
        if (lane == 0) {
            reinterpret_cast<float4*>(out)[(long)warp * 2 + 0] =
                make_float4(y[0] + bs[0], y[1] + bs[1], y[2] + bs[2], y[3] + bs[3]);
            reinterpret_cast<float4*>(out)[(long)warp * 2 + 1] =
                make_float4(y[4] + bs[4], y[5] + bs[5], y[6] + bs[6], y[7] + bs[7]);
        }
    }
}

// ---------------------------------------------------------------------------
// Launcher
// ---------------------------------------------------------------------------
extern "C" void kernel_launch(void* const* d_in, const int* in_sizes, int n_in,
                              void* d_out, int out_size) {
    const float* x   = (const float*)d_in[0];
    const int*   ei  = (const int*)d_in[1];   // int32 view; stride handles int64
    const float* W1  = (const float*)d_in[2];
    const float* b1  = (const float*)d_in[3];
    const float* W2  = (const float*)d_in[4];
    const float* b2  = (const float*)d_in[5];
    const float* Wfc = (const float*)d_in[6];
    const float* bfc = (const float*)d_in[7];
    float*       out = (float*)d_out;

    const int n = in_sizes[0] / 128;
    const int e = in_sizes[1] / 2;

    const int T = 256;
    int gn  = (n + T - 1) / T;
    int ge  = (e + T - 1) / T;
    int gg  = (n + 127) / 128;
    int gag = (n + 7) / 8;           // 8 warps per block

    // 1) CSR build + normalization (4 launches)
    k_init<<<gn, T>>>(ei, n);
    k_hist<<<ge, T>>>(ei, e, n);
    k_scan<<<1, 1024>>>(n);
    k_fill<<<ge, T>>>(ei, e, n);

    // 2) layer 1
    k_gemm128<<<gg, T>>>(x, W1, 1, n);                     // bufA = x @ W1
    k_aggregate<<<gag, T>>>(b1, nullptr, nullptr, nullptr, n);  // bufB = agg+b1

    // 3) layer 2 + fused classifier
    k_gemm128<<<gg, T>>>(nullptr, W2, 0, n);               // bufA = bufB @ W2
    k_aggregate<<<gag, T>>>(b2, Wfc, bfc, out, n);         // out = (agg+b2)@Wfc+bfc
}